// round 1
// baseline (speedup 1.0000x reference)
#include <cuda_runtime.h>
#include <cuda_bf16.h>
#include <cstdint>

// Problem constants (dataset-fixed shapes; N/E/B derived from in_sizes at launch)
#define NMAX   50048      // 391 * 128, >= N=50000
#define DH     192        // hom_conv_dim (3 kernels x 64)
#define DK     64
#define BMAXP  256        // max graphs for pooled buffer

// ---------------- scratch (static device globals; no allocation) ----------------
__device__ float g_h0[NMAX * DH];     // layer0 linear outputs (concat of 3 kernels)
__device__ float g_f1[NMAX * DH];     // layer0 aggregated (pre-relu)
__device__ float g_h1[NMAX * DH];     // layer1 linear outputs
__device__ float g_f2[NMAX * DH];     // layer1 aggregated (pre-relu)
__device__ float g_pool[BMAXP * DH];  // pooled per-graph sums

// ---------------- zero-init f1, f2, pooled ----------------
__global__ void zero_all_kernel(int n4_feat, int n4_pool) {
    int i = blockIdx.x * blockDim.x + threadIdx.x;
    float4 z = make_float4(0.f, 0.f, 0.f, 0.f);
    if (i < n4_feat) {
        reinterpret_cast<float4*>(g_f1)[i] = z;
        reinterpret_cast<float4*>(g_f2)[i] = z;
    }
    if (i < n4_pool) {
        reinterpret_cast<float4*>(g_pool)[i] = z;
    }
}

// ---------------- SGEMM: C[:, mker*64 : +64] = act(X) @ W_mker + b_mker ----------
// X: [N, K] row-major.  W: [K, 64] row-major.  C: [N, 192] row-major.
// BM=128, BN=64, BK=16, 256 threads, 8x4 thread tile.
template <bool RELU_IN>
__global__ __launch_bounds__(256, 2)
void gemm_kernel(const float* __restrict__ X, int N, int K,
                 const float* __restrict__ W0, const float* __restrict__ W1,
                 const float* __restrict__ W2,
                 const float* __restrict__ b0, const float* __restrict__ b1,
                 const float* __restrict__ b2,
                 float* __restrict__ C)
{
    const int m0   = blockIdx.x * 128;
    const int mker = blockIdx.y;                    // which hom-kernel (0..2)
    const float* __restrict__ W    = (mker == 0) ? W0 : (mker == 1 ? W1 : W2);
    const float* __restrict__ bias = (mker == 0) ? b0 : (mker == 1 ? b1 : b2);

    __shared__ float As[128][16];   // [m][k]
    __shared__ float Bs[16][64];    // [k][n]

    const int t  = threadIdx.x;
    const int tx = t & 15;          // n-tile index (n = tx*4)
    const int ty = t >> 4;          // m-tile index (m = ty*8)

    float4 acc[8];
#pragma unroll
    for (int i = 0; i < 8; ++i) acc[i] = make_float4(0.f, 0.f, 0.f, 0.f);

    for (int kk = 0; kk < K; kk += 16) {
        // load X tile: 128 rows x 16 k = 512 float4; 2 per thread
#pragma unroll
        for (int it = 0; it < 2; ++it) {
            int idx = t + it * 256;
            int row = idx >> 2;
            int c4  = idx & 3;
            int gr  = m0 + row;
            float4 v = make_float4(0.f, 0.f, 0.f, 0.f);
            if (gr < N) {
                v = *reinterpret_cast<const float4*>(&X[(long)gr * K + kk + c4 * 4]);
                if (RELU_IN) {
                    v.x = fmaxf(v.x, 0.f); v.y = fmaxf(v.y, 0.f);
                    v.z = fmaxf(v.z, 0.f); v.w = fmaxf(v.w, 0.f);
                }
            }
            *reinterpret_cast<float4*>(&As[row][c4 * 4]) = v;
        }
        // load W tile: 16 k x 64 n = 256 float4; 1 per thread
        {
            int k  = t >> 4;
            int n4 = t & 15;
            float4 w = *reinterpret_cast<const float4*>(&W[(long)(kk + k) * 64 + n4 * 4]);
            *reinterpret_cast<float4*>(&Bs[k][n4 * 4]) = w;
        }
        __syncthreads();

#pragma unroll
        for (int k4 = 0; k4 < 4; ++k4) {
            float4 bq[4];
#pragma unroll
            for (int j = 0; j < 4; ++j)
                bq[j] = *reinterpret_cast<const float4*>(&Bs[k4 * 4 + j][tx * 4]);
#pragma unroll
            for (int i = 0; i < 8; ++i) {
                float4 av = *reinterpret_cast<const float4*>(&As[ty * 8 + i][k4 * 4]);
                acc[i].x += av.x * bq[0].x; acc[i].y += av.x * bq[0].y;
                acc[i].z += av.x * bq[0].z; acc[i].w += av.x * bq[0].w;
                acc[i].x += av.y * bq[1].x; acc[i].y += av.y * bq[1].y;
                acc[i].z += av.y * bq[1].z; acc[i].w += av.y * bq[1].w;
                acc[i].x += av.z * bq[2].x; acc[i].y += av.z * bq[2].y;
                acc[i].z += av.z * bq[2].z; acc[i].w += av.z * bq[2].w;
                acc[i].x += av.w * bq[3].x; acc[i].y += av.w * bq[3].y;
                acc[i].z += av.w * bq[3].z; acc[i].w += av.w * bq[3].w;
            }
        }
        __syncthreads();
    }

    // epilogue: + bias, store into [N, 192] at column offset mker*64
    float4 bb = *reinterpret_cast<const float4*>(&bias[tx * 4]);
#pragma unroll
    for (int i = 0; i < 8; ++i) {
        int row = m0 + ty * 8 + i;
        if (row < N) {
            float4 v = acc[i];
            v.x += bb.x; v.y += bb.y; v.z += bb.z; v.w += bb.w;
            *reinterpret_cast<float4*>(&C[(long)row * DH + mker * 64 + tx * 4]) = v;
        }
    }
}

// ---------------- gather + scatter_add over edges -------------------------------
// mapping layout: [2, E] int32 row-major; row0 = dst (root), row1 = src (image).
// 16 threads per edge, each handling one float4 of the 64-wide slice.
__global__ __launch_bounds__(256)
void scatter_kernel(const float* __restrict__ h,
                    const int* __restrict__ mA,
                    const int* __restrict__ mB,
                    const int* __restrict__ mC,
                    int E, float* __restrict__ out)
{
    const int* __restrict__ mp =
        (blockIdx.y == 0) ? mA : (blockIdx.y == 1 ? mB : mC);
    const int moff = blockIdx.y * 64;

    int tid = blockIdx.x * 256 + threadIdx.x;
    int e = tid >> 4;
    int q = tid & 15;
    if (e >= E) return;

    int dst = mp[e];
    int src = mp[E + e];

    float4 v = *reinterpret_cast<const float4*>(&h[(long)src * DH + moff + q * 4]);
    float* o = &out[(long)dst * DH + moff + q * 4];
    asm volatile("red.global.add.v4.f32 [%0], {%1, %2, %3, %4};"
                 :: "l"(o), "f"(v.x), "f"(v.y), "f"(v.z), "f"(v.w)
                 : "memory");
}

// ---------------- batch pooling (batch_idx is sorted) ----------------------------
// block handles 128 nodes; 192 threads, one per feature column; register-accumulate
// within a graph segment, atomic only on segment transitions.
__global__ __launch_bounds__(192)
void pool_kernel(const float* __restrict__ f2, const int* __restrict__ bidx,
                 int N, float* __restrict__ pooled)
{
    __shared__ int sb[128];
    const int n0 = blockIdx.x * 128;
    const int t  = threadIdx.x;
    const int nEnd = min(n0 + 128, N);
    if (n0 >= N) return;
    if (t < 128 && (n0 + t) < N) sb[t] = bidx[n0 + t];
    __syncthreads();

    int cur = sb[0];
    float acc = 0.f;
    for (int n = n0; n < nEnd; ++n) {
        int b = sb[n - n0];
        if (b != cur) {
            atomicAdd(&pooled[cur * DH + t], acc);
            acc = 0.f;
            cur = b;
        }
        acc += fmaxf(f2[(long)n * DH + t], 0.f);
    }
    atomicAdd(&pooled[cur * DH + t], acc);
}

// ---------------- final MLP: relu(pooled @ A1 + ba1) @ A2 + ba2 ------------------
__global__ __launch_bounds__(256)
void mlp_kernel(const float* __restrict__ pooled,
                const float* __restrict__ A1, const float* __restrict__ ba1,
                const float* __restrict__ A2, const float* __restrict__ ba2,
                float* __restrict__ out)
{
    const int g = blockIdx.x;
    __shared__ float sp[DH];
    __shared__ float sh[256];
    const int t = threadIdx.x;
    if (t < DH) sp[t] = pooled[g * DH + t];
    __syncthreads();

    float acc = ba1[t];
#pragma unroll 8
    for (int k = 0; k < DH; ++k)
        acc += sp[k] * A1[k * 256 + t];
    sh[t] = fmaxf(acc, 0.f);
    __syncthreads();

    if (t < 10) {
        float o = ba2[t];
#pragma unroll 8
        for (int j = 0; j < 256; ++j)
            o += sh[j] * A2[j * 10 + t];
        out[g * 10 + t] = o;
    }
}

// ---------------- launcher -------------------------------------------------------
extern "C" void kernel_launch(void* const* d_in, const int* in_sizes, int n_in,
                              void* d_out, int out_size)
{
    const float* x     = (const float*)d_in[0];
    const int*   map00 = (const int*)d_in[1];
    const int*   map01 = (const int*)d_in[2];
    const int*   map02 = (const int*)d_in[3];
    const int*   map10 = (const int*)d_in[4];
    const int*   map11 = (const int*)d_in[5];
    const int*   map12 = (const int*)d_in[6];
    const int*   bidx  = (const int*)d_in[7];
    // d_in[8] = batch_size scalar (B derived from out_size instead)
    const float* W00 = (const float*)d_in[9];
    const float* b00 = (const float*)d_in[10];
    const float* W01 = (const float*)d_in[11];
    const float* b01 = (const float*)d_in[12];
    const float* W02 = (const float*)d_in[13];
    const float* b02 = (const float*)d_in[14];
    const float* W10 = (const float*)d_in[15];
    const float* b10 = (const float*)d_in[16];
    const float* W11 = (const float*)d_in[17];
    const float* b11 = (const float*)d_in[18];
    const float* W12 = (const float*)d_in[19];
    const float* b12 = (const float*)d_in[20];
    const float* A1  = (const float*)d_in[21];
    const float* ba1 = (const float*)d_in[22];
    const float* A2  = (const float*)d_in[23];
    const float* ba2 = (const float*)d_in[24];

    const int DIN = 128;
    const int N = in_sizes[0] / DIN;
    const int E = in_sizes[1] / 2;
    const int B = out_size / 10;

    float *p_h0, *p_f1, *p_h1, *p_f2, *p_pool;
    cudaGetSymbolAddress((void**)&p_h0, g_h0);
    cudaGetSymbolAddress((void**)&p_f1, g_f1);
    cudaGetSymbolAddress((void**)&p_h1, g_h1);
    cudaGetSymbolAddress((void**)&p_f2, g_f2);
    cudaGetSymbolAddress((void**)&p_pool, g_pool);

    // 1) zero f1, f2, pooled
    {
        int n4_feat = N * DH / 4;
        int n4_pool = B * DH / 4;
        int blocks = (n4_feat + 255) / 256;
        zero_all_kernel<<<blocks, 256>>>(n4_feat, n4_pool);
    }

    const int mBlocks = (N + 127) / 128;

    // 2) layer0 linear: h0 = x @ [W00|W01|W02] + b
    gemm_kernel<false><<<dim3(mBlocks, 3), 256>>>(
        x, N, DIN, W00, W01, W02, b00, b01, b02, p_h0);

    // 3) layer0 scatter: f1[dst] += h0[src]  (per mapping, per 64-col slice)
    {
        int blocks = (E * 16 + 255) / 256;
        scatter_kernel<<<dim3(blocks, 3), 256>>>(p_h0, map00, map01, map02, E, p_f1);
    }

    // 4) layer1 linear (relu fused on input): h1 = relu(f1) @ [W10|W11|W12] + b
    gemm_kernel<true><<<dim3(mBlocks, 3), 256>>>(
        p_f1, N, DH, W10, W11, W12, b10, b11, b12, p_h1);

    // 5) layer1 scatter: f2[dst] += h1[src]
    {
        int blocks = (E * 16 + 255) / 256;
        scatter_kernel<<<dim3(blocks, 3), 256>>>(p_h1, map10, map11, map12, E, p_f2);
    }

    // 6) pooling (relu fused): pooled[b] += relu(f2[n])
    pool_kernel<<<mBlocks, 192>>>(p_f2, bidx, N, p_pool);

    // 7) MLP head
    mlp_kernel<<<B, 256>>>(p_pool, A1, ba1, A2, ba2, (float*)d_out);
}

// round 2
// speedup vs baseline: 1.3985x; 1.3985x over previous
#include <cuda_runtime.h>
#include <cuda_fp16.h>
#include <cstdint>

#define NMAX   50048
#define DH     192
#define BMAXP  256

// ---------------- scratch (static device globals) ----------------
__device__ __half g_h0[NMAX * DH];   // layer0 linear outputs (fp16)
__device__ __half g_f1[NMAX * DH];   // layer0 aggregated (fp16, atomic target)
__device__ __half g_h1[NMAX * DH];   // layer1 linear outputs (fp16)
__device__ __half g_f2[NMAX * DH];   // layer1 aggregated (fp16, atomic target)
__device__ float  g_pool[BMAXP * DH];

// ---------------- zero f1, f2 (half), pooled (fp32) ----------------
__global__ void zero_all_kernel(int n16_feat, int n4_pool) {
    int i = blockIdx.x * blockDim.x + threadIdx.x;
    uint4 z = make_uint4(0u, 0u, 0u, 0u);
    if (i < n16_feat) {
        reinterpret_cast<uint4*>(g_f1)[i] = z;
        reinterpret_cast<uint4*>(g_f2)[i] = z;
    }
    if (i < n4_pool) {
        reinterpret_cast<float4*>(g_pool)[i] = make_float4(0.f, 0.f, 0.f, 0.f);
    }
}

// ---------------- SGEMM: C[:, mker*64 : +64] = act(X) @ W_mker + b_mker ----------
// BM=256, BN=64, BK=16, 256 threads, 8x8 thread tile. Output fp16 into [N,192].
// TIN = float (layer0, no relu) or __half (layer1, relu on load).
template <typename TIN, bool RELU>
__global__ __launch_bounds__(256, 2)
void gemm_kernel(const TIN* __restrict__ X, int N, int K,
                 const float* __restrict__ W0, const float* __restrict__ W1,
                 const float* __restrict__ W2,
                 const float* __restrict__ b0, const float* __restrict__ b1,
                 const float* __restrict__ b2,
                 __half* __restrict__ C)
{
    const int m0   = blockIdx.x * 256;
    const int mker = blockIdx.y;
    const float* __restrict__ W    = (mker == 0) ? W0 : (mker == 1 ? W1 : W2);
    const float* __restrict__ bias = (mker == 0) ? b0 : (mker == 1 ? b1 : b2);

    __shared__ float As[16][256];   // [k][row]
    __shared__ float Bs[16][64];    // [k][n]

    const int t  = threadIdx.x;
    const int tx = t & 7;           // n-octet: cols tx*8 .. +8
    const int ty = t >> 3;          // m-octet: rows ty*8 .. +8

    float acc[8][8];
#pragma unroll
    for (int i = 0; i < 8; ++i)
#pragma unroll
        for (int j = 0; j < 8; ++j) acc[i][j] = 0.f;

    for (int kk = 0; kk < K; kk += 16) {
        // ---- load A panel: 256 rows x 16 k ----
        if constexpr (sizeof(TIN) == 4) {
            // fp32 input: 1024 float4, 4 per thread
#pragma unroll
            for (int it = 0; it < 4; ++it) {
                int idx = t + it * 256;
                int row = idx >> 2;
                int c4  = idx & 3;
                int gr  = m0 + row;
                float4 v = make_float4(0.f, 0.f, 0.f, 0.f);
                if (gr < N)
                    v = *reinterpret_cast<const float4*>(
                        &((const float*)X)[(long)gr * K + kk + c4 * 4]);
                As[c4 * 4 + 0][row] = v.x;
                As[c4 * 4 + 1][row] = v.y;
                As[c4 * 4 + 2][row] = v.z;
                As[c4 * 4 + 3][row] = v.w;
            }
        } else {
            // fp16 input: 512 uint4 (8 halves each), 2 per thread
#pragma unroll
            for (int it = 0; it < 2; ++it) {
                int idx = t + it * 256;
                int row = idx >> 1;
                int hp  = idx & 1;           // which 8-half chunk of the k-panel
                int gr  = m0 + row;
                uint4 u = make_uint4(0u, 0u, 0u, 0u);
                if (gr < N)
                    u = *reinterpret_cast<const uint4*>(
                        &((const __half*)X)[(long)gr * K + kk + hp * 8]);
                const __half2* hh = reinterpret_cast<const __half2*>(&u);
#pragma unroll
                for (int j = 0; j < 4; ++j) {
                    float2 f = __half22float2(hh[j]);
                    if (RELU) { f.x = fmaxf(f.x, 0.f); f.y = fmaxf(f.y, 0.f); }
                    As[hp * 8 + j * 2 + 0][row] = f.x;
                    As[hp * 8 + j * 2 + 1][row] = f.y;
                }
            }
        }
        // ---- load B panel: 16 k x 64 n = 256 float4, 1 per thread ----
        {
            int k  = t >> 4;
            int n4 = t & 15;
            float4 w = *reinterpret_cast<const float4*>(&W[(long)(kk + k) * 64 + n4 * 4]);
            *reinterpret_cast<float4*>(&Bs[k][n4 * 4]) = w;
        }
        __syncthreads();

#pragma unroll
        for (int k = 0; k < 16; ++k) {
            float a[8], b[8];
            *reinterpret_cast<float4*>(&a[0]) = *reinterpret_cast<const float4*>(&As[k][ty * 8]);
            *reinterpret_cast<float4*>(&a[4]) = *reinterpret_cast<const float4*>(&As[k][ty * 8 + 4]);
            *reinterpret_cast<float4*>(&b[0]) = *reinterpret_cast<const float4*>(&Bs[k][tx * 8]);
            *reinterpret_cast<float4*>(&b[4]) = *reinterpret_cast<const float4*>(&Bs[k][tx * 8 + 4]);
#pragma unroll
            for (int i = 0; i < 8; ++i)
#pragma unroll
                for (int j = 0; j < 8; ++j)
                    acc[i][j] += a[i] * b[j];
        }
        __syncthreads();
    }

    // ---- epilogue: + bias, convert to fp16, store 16B per row ----
    float bb[8];
#pragma unroll
    for (int j = 0; j < 8; ++j) bb[j] = bias[tx * 8 + j];

#pragma unroll
    for (int i = 0; i < 8; ++i) {
        int row = m0 + ty * 8 + i;
        if (row < N) {
            __half2 h2[4];
#pragma unroll
            for (int j = 0; j < 4; ++j)
                h2[j] = __floats2half2_rn(acc[i][j * 2] + bb[j * 2],
                                          acc[i][j * 2 + 1] + bb[j * 2 + 1]);
            *reinterpret_cast<uint4*>(&C[(long)row * DH + mker * 64 + tx * 8]) =
                *reinterpret_cast<uint4*>(h2);
        }
    }
}

// ---------------- gather + scatter_add over edges (fp16, v4.f16x2 red) -----------
// 8 threads per edge, each handling 8 halves (16B). Block = 32 edges.
__global__ __launch_bounds__(256)
void scatter_kernel(const __half* __restrict__ h,
                    const int* __restrict__ mA,
                    const int* __restrict__ mB,
                    const int* __restrict__ mC,
                    int E, __half* __restrict__ out)
{
    const int* __restrict__ mp =
        (blockIdx.y == 0) ? mA : (blockIdx.y == 1 ? mB : mC);
    const int moff = blockIdx.y * 64;

    __shared__ int sd[32], ss[32];
    const int e0 = blockIdx.x * 32;
    const int t  = threadIdx.x;
    if (t < 32) {
        int e = e0 + t;
        sd[t] = (e < E) ? mp[e] : -1;
    } else if (t < 64) {
        int e = e0 + t - 32;
        ss[t - 32] = (e < E) ? mp[E + e] : 0;
    }
    __syncthreads();

    const int le = t >> 3;      // local edge 0..31
    const int q  = t & 7;       // 16B chunk within 64-col slice
    const int dst = sd[le];
    if (dst < 0) return;
    const int src = ss[le];

    uint4 v = *reinterpret_cast<const uint4*>(&h[(long)src * DH + moff + q * 8]);
    const __half* o = &out[(long)dst * DH + moff + q * 8];
    asm volatile("red.global.add.noftz.v4.f16x2 [%0], {%1, %2, %3, %4};"
                 :: "l"(o), "r"(v.x), "r"(v.y), "r"(v.z), "r"(v.w)
                 : "memory");
}

// ---------------- batch pooling (batch_idx sorted; relu fused) -------------------
__global__ __launch_bounds__(192)
void pool_kernel(const __half* __restrict__ f2, const int* __restrict__ bidx,
                 int N, float* __restrict__ pooled)
{
    __shared__ int sb[128];
    const int n0 = blockIdx.x * 128;
    const int t  = threadIdx.x;
    if (n0 >= N) return;
    const int nEnd = min(n0 + 128, N);
    if (t < 128 && (n0 + t) < N) sb[t] = bidx[n0 + t];
    __syncthreads();

    int cur = sb[0];
    float acc = 0.f;
    for (int n = n0; n < nEnd; ++n) {
        int b = sb[n - n0];
        if (b != cur) {
            atomicAdd(&pooled[cur * DH + t], acc);
            acc = 0.f;
            cur = b;
        }
        acc += fmaxf(__half2float(f2[(long)n * DH + t]), 0.f);
    }
    atomicAdd(&pooled[cur * DH + t], acc);
}

// ---------------- final MLP ------------------------------------------------------
__global__ __launch_bounds__(256)
void mlp_kernel(const float* __restrict__ pooled,
                const float* __restrict__ A1, const float* __restrict__ ba1,
                const float* __restrict__ A2, const float* __restrict__ ba2,
                float* __restrict__ out)
{
    const int g = blockIdx.x;
    __shared__ float sp[DH];
    __shared__ float sh[256];
    const int t = threadIdx.x;
    if (t < DH) sp[t] = pooled[g * DH + t];
    __syncthreads();

    float acc = ba1[t];
#pragma unroll 8
    for (int k = 0; k < DH; ++k)
        acc += sp[k] * A1[k * 256 + t];
    sh[t] = fmaxf(acc, 0.f);
    __syncthreads();

    if (t < 10) {
        float o = ba2[t];
#pragma unroll 8
        for (int j = 0; j < 256; ++j)
            o += sh[j] * A2[j * 10 + t];
        out[g * 10 + t] = o;
    }
}

// ---------------- launcher -------------------------------------------------------
extern "C" void kernel_launch(void* const* d_in, const int* in_sizes, int n_in,
                              void* d_out, int out_size)
{
    const float* x     = (const float*)d_in[0];
    const int*   map00 = (const int*)d_in[1];
    const int*   map01 = (const int*)d_in[2];
    const int*   map02 = (const int*)d_in[3];
    const int*   map10 = (const int*)d_in[4];
    const int*   map11 = (const int*)d_in[5];
    const int*   map12 = (const int*)d_in[6];
    const int*   bidx  = (const int*)d_in[7];
    const float* W00 = (const float*)d_in[9];
    const float* b00 = (const float*)d_in[10];
    const float* W01 = (const float*)d_in[11];
    const float* b01 = (const float*)d_in[12];
    const float* W02 = (const float*)d_in[13];
    const float* b02 = (const float*)d_in[14];
    const float* W10 = (const float*)d_in[15];
    const float* b10 = (const float*)d_in[16];
    const float* W11 = (const float*)d_in[17];
    const float* b11 = (const float*)d_in[18];
    const float* W12 = (const float*)d_in[19];
    const float* b12 = (const float*)d_in[20];
    const float* A1  = (const float*)d_in[21];
    const float* ba1 = (const float*)d_in[22];
    const float* A2  = (const float*)d_in[23];
    const float* ba2 = (const float*)d_in[24];

    const int DIN = 128;
    const int N = in_sizes[0] / DIN;
    const int E = in_sizes[1] / 2;
    const int B = out_size / 10;

    __half *p_h0, *p_f1, *p_h1, *p_f2;
    float  *p_pool;
    cudaGetSymbolAddress((void**)&p_h0, g_h0);
    cudaGetSymbolAddress((void**)&p_f1, g_f1);
    cudaGetSymbolAddress((void**)&p_h1, g_h1);
    cudaGetSymbolAddress((void**)&p_f2, g_f2);
    cudaGetSymbolAddress((void**)&p_pool, g_pool);

    // 1) zero f1, f2 (half), pooled (fp32)
    {
        int n16_feat = N * DH / 8;       // uint4 count over halves
        int n4_pool  = B * DH / 4;
        int blocks = (n16_feat + 255) / 256;
        zero_all_kernel<<<blocks, 256>>>(n16_feat, n4_pool);
    }

    const int mBlocks = (N + 255) / 256;

    // 2) layer0 linear: h0 = x @ [W00|W01|W02] + b   (fp32 in, fp16 out)
    gemm_kernel<float, false><<<dim3(mBlocks, 3), 256>>>(
        x, N, DIN, W00, W01, W02, b00, b01, b02, p_h0);

    // 3) layer0 scatter: f1[dst] += h0[src]
    {
        int blocks = (E + 31) / 32;
        scatter_kernel<<<dim3(blocks, 3), 256>>>(p_h0, map00, map01, map02, E, p_f1);
    }

    // 4) layer1 linear: h1 = relu(f1) @ [W10|W11|W12] + b   (fp16 in, fp16 out)
    gemm_kernel<__half, true><<<dim3(mBlocks, 3), 256>>>(
        p_f1, N, DH, W10, W11, W12, b10, b11, b12, p_h1);

    // 5) layer1 scatter: f2[dst] += h1[src]
    {
        int blocks = (E + 31) / 32;
        scatter_kernel<<<dim3(blocks, 3), 256>>>(p_h1, map10, map11, map12, E, p_f2);
    }

    // 6) pooling (relu fused)
    pool_kernel<<<(N + 127) / 128, 192>>>(p_f2, bidx, N, p_pool);

    // 7) MLP head
    mlp_kernel<<<B, 256>>>(p_pool, A1, ba1, A2, ba2, (float*)d_out);
}

// round 10
// speedup vs baseline: 1.8636x; 1.3325x over previous
#include <cuda_runtime.h>
#include <cuda_fp16.h>
#include <cstdint>

#define NMAX   50048
#define DH     192
#define BMAXP  256

// ---------------- scratch (static device globals) ----------------
__device__ __half g_h0[NMAX * DH];
__device__ __half g_f1[NMAX * DH];
__device__ __half g_h1[NMAX * DH];
__device__ __half g_f2[NMAX * DH];
__device__ float  g_pool[BMAXP * DH];

// ---------------- zero f1, f2 (half), pooled (fp32) ----------------
__global__ void zero_all_kernel(int n16_feat, int n4_pool) {
    int i = blockIdx.x * blockDim.x + threadIdx.x;
    uint4 z = make_uint4(0u, 0u, 0u, 0u);
    if (i < n16_feat) {
        reinterpret_cast<uint4*>(g_f1)[i] = z;
        reinterpret_cast<uint4*>(g_f2)[i] = z;
    }
    if (i < n4_pool) {
        reinterpret_cast<float4*>(g_pool)[i] = make_float4(0.f, 0.f, 0.f, 0.f);
    }
}

// ---------------- HMMA helpers ----------------
__device__ __forceinline__ uint32_t smem_u32(const void* p) {
    return (uint32_t)__cvta_generic_to_shared(p);
}
__device__ __forceinline__ void ldm_x4(uint32_t& r0, uint32_t& r1, uint32_t& r2,
                                       uint32_t& r3, uint32_t addr) {
    asm volatile("ldmatrix.sync.aligned.m8n8.x4.shared.b16 {%0,%1,%2,%3}, [%4];"
                 : "=r"(r0), "=r"(r1), "=r"(r2), "=r"(r3) : "r"(addr));
}
__device__ __forceinline__ void ldm_x4_t(uint32_t& r0, uint32_t& r1, uint32_t& r2,
                                         uint32_t& r3, uint32_t addr) {
    asm volatile("ldmatrix.sync.aligned.m8n8.x4.trans.shared.b16 {%0,%1,%2,%3}, [%4];"
                 : "=r"(r0), "=r"(r1), "=r"(r2), "=r"(r3) : "r"(addr));
}
__device__ __forceinline__ void mma16816(float* d, const uint32_t* a, const uint32_t* b) {
    asm volatile(
        "mma.sync.aligned.m16n8k16.row.col.f32.f16.f16.f32 "
        "{%0,%1,%2,%3}, {%4,%5,%6,%7}, {%8,%9}, {%0,%1,%2,%3};"
        : "+f"(d[0]), "+f"(d[1]), "+f"(d[2]), "+f"(d[3])
        : "r"(a[0]), "r"(a[1]), "r"(a[2]), "r"(a[3]), "r"(b[0]), "r"(b[1]));
}

// ---------------- tensor-core GEMM -------------------------------------------
// C[:, mker*64 : +64] = act(X) @ W_mker + b_mker    (fp32 accum, fp16 out)
// BM=128, BN=64, BK=32, 256 threads = 8 warps (4m x 2n), each warp 32x32.
#define A_STR 40   // halves per A smem row (pad 32 -> 40)
#define B_STR 72   // halves per B smem row (pad 64 -> 72)

template <typename TIN, bool RELU>
__global__ __launch_bounds__(256, 2)
void gemm_tc_kernel(const TIN* __restrict__ X, int N, int K,
                    const float* __restrict__ W0, const float* __restrict__ W1,
                    const float* __restrict__ W2,
                    const float* __restrict__ b0, const float* __restrict__ b1,
                    const float* __restrict__ b2,
                    __half* __restrict__ C)
{
    const int m0   = blockIdx.x * 128;
    const int mker = blockIdx.y;
    const float* __restrict__ W    = (mker == 0) ? W0 : (mker == 1 ? W1 : W2);
    const float* __restrict__ bias = (mker == 0) ? b0 : (mker == 1 ? b1 : b2);

    __shared__ __half As[128][A_STR];
    __shared__ __half Bs[32][B_STR];

    const int t    = threadIdx.x;
    const int lane = t & 31;
    const int wid  = t >> 5;
    const int wm   = wid >> 1;   // 0..3 -> rows wm*32
    const int wn   = wid & 1;    // 0..1 -> cols wn*32

    float acc[2][4][4];
#pragma unroll
    for (int i = 0; i < 2; ++i)
#pragma unroll
        for (int j = 0; j < 4; ++j)
#pragma unroll
            for (int q = 0; q < 4; ++q) acc[i][j][q] = 0.f;

    for (int kk = 0; kk < K; kk += 32) {
        // ---- A tile: 128 rows x 32 k -> fp16 smem ----
        if constexpr (sizeof(TIN) == 4) {
            // fp32 in: 128*8 float4, 4 per thread
#pragma unroll
            for (int it = 0; it < 4; ++it) {
                int idx = t + it * 256;
                int row = idx >> 3;
                int c4  = idx & 7;
                int gr  = m0 + row;
                float4 v = make_float4(0.f, 0.f, 0.f, 0.f);
                if (gr < N)
                    v = *reinterpret_cast<const float4*>(
                        &((const float*)X)[(long)gr * K + kk + c4 * 4]);
                __half2 h01 = __floats2half2_rn(v.x, v.y);
                __half2 h23 = __floats2half2_rn(v.z, v.w);
                *reinterpret_cast<__half2*>(&As[row][c4 * 4])     = h01;
                *reinterpret_cast<__half2*>(&As[row][c4 * 4 + 2]) = h23;
            }
        } else {
            // fp16 in: 128*4 uint4, 2 per thread (relu on load)
#pragma unroll
            for (int it = 0; it < 2; ++it) {
                int idx = t + it * 256;
                int row = idx >> 2;
                int hp  = idx & 3;
                int gr  = m0 + row;
                uint4 u = make_uint4(0u, 0u, 0u, 0u);
                if (gr < N)
                    u = *reinterpret_cast<const uint4*>(
                        &((const __half*)X)[(long)gr * K + kk + hp * 8]);
                if (RELU) {
                    __half2* hh = reinterpret_cast<__half2*>(&u);
                    __half2 z = __float2half2_rn(0.f);
#pragma unroll
                    for (int j = 0; j < 4; ++j) hh[j] = __hmax2(hh[j], z);
                }
                *reinterpret_cast<uint4*>(&As[row][hp * 8]) = u;
            }
        }
        // ---- B tile: 32 k x 64 n fp32 -> fp16 smem ----
#pragma unroll
        for (int it = 0; it < 2; ++it) {
            int idx = t + it * 256;
            int k   = idx >> 4;
            int n4  = idx & 15;
            float4 w = *reinterpret_cast<const float4*>(&W[(long)(kk + k) * 64 + n4 * 4]);
            __half2 h01 = __floats2half2_rn(w.x, w.y);
            __half2 h23 = __floats2half2_rn(w.z, w.w);
            *reinterpret_cast<__half2*>(&Bs[k][n4 * 4])     = h01;
            *reinterpret_cast<__half2*>(&Bs[k][n4 * 4 + 2]) = h23;
        }
        __syncthreads();

#pragma unroll
        for (int k16 = 0; k16 < 32; k16 += 16) {
            uint32_t af[2][4];
#pragma unroll
            for (int mi = 0; mi < 2; ++mi) {
                uint32_t addr = smem_u32(&As[wm * 32 + mi * 16 + (lane & 15)]
                                            [k16 + (lane >> 4) * 8]);
                ldm_x4(af[mi][0], af[mi][1], af[mi][2], af[mi][3], addr);
            }
            uint32_t bf[4][2];
#pragma unroll
            for (int ni2 = 0; ni2 < 2; ++ni2) {
                int n0 = wn * 32 + ni2 * 16;
                uint32_t addr = smem_u32(&Bs[k16 + (lane & 15)][n0 + (lane >> 4) * 8]);
                uint32_t r0, r1, r2, r3;
                ldm_x4_t(r0, r1, r2, r3, addr);
                bf[ni2 * 2][0]     = r0; bf[ni2 * 2][1]     = r1;
                bf[ni2 * 2 + 1][0] = r2; bf[ni2 * 2 + 1][1] = r3;
            }
#pragma unroll
            for (int mi = 0; mi < 2; ++mi)
#pragma unroll
                for (int ni = 0; ni < 4; ++ni)
                    mma16816(acc[mi][ni], af[mi], bf[ni]);
        }
        __syncthreads();
    }

    // ---- epilogue: + bias, fp16 store ----
#pragma unroll
    for (int mi = 0; mi < 2; ++mi) {
#pragma unroll
        for (int ni = 0; ni < 4; ++ni) {
            int col = wn * 32 + ni * 8 + (lane & 3) * 2;
            float bx = bias[col], by = bias[col + 1];
            int r0 = m0 + wm * 32 + mi * 16 + (lane >> 2);
            if (r0 < N) {
                __half2 h = __floats2half2_rn(acc[mi][ni][0] + bx, acc[mi][ni][1] + by);
                *reinterpret_cast<__half2*>(&C[(long)r0 * DH + mker * 64 + col]) = h;
            }
            int r1 = r0 + 8;
            if (r1 < N) {
                __half2 h = __floats2half2_rn(acc[mi][ni][2] + bx, acc[mi][ni][3] + by);
                *reinterpret_cast<__half2*>(&C[(long)r1 * DH + mker * 64 + col]) = h;
            }
        }
    }
}

// ---------------- gather + scatter_add over edges (fp16, v4.f16x2 red) -----------
__global__ __launch_bounds__(256)
void scatter_kernel(const __half* __restrict__ h,
                    const int* __restrict__ mA,
                    const int* __restrict__ mB,
                    const int* __restrict__ mC,
                    int E, __half* __restrict__ out)
{
    const int* __restrict__ mp =
        (blockIdx.y == 0) ? mA : (blockIdx.y == 1 ? mB : mC);
    const int moff = blockIdx.y * 64;

    __shared__ int sd[32], ss[32];
    const int e0 = blockIdx.x * 32;
    const int t  = threadIdx.x;
    if (t < 32) {
        int e = e0 + t;
        sd[t] = (e < E) ? mp[e] : -1;
    } else if (t < 64) {
        int e = e0 + t - 32;
        ss[t - 32] = (e < E) ? mp[E + e] : 0;
    }
    __syncthreads();

    const int le = t >> 3;
    const int q  = t & 7;
    const int dst = sd[le];
    if (dst < 0) return;
    const int src = ss[le];

    uint4 v = *reinterpret_cast<const uint4*>(&h[(long)src * DH + moff + q * 8]);
    const __half* o = &out[(long)dst * DH + moff + q * 8];
    asm volatile("red.global.add.noftz.v4.f16x2 [%0], {%1, %2, %3, %4};"
                 :: "l"(o), "r"(v.x), "r"(v.y), "r"(v.z), "r"(v.w)
                 : "memory");
}

// ---------------- batch pooling (batch_idx sorted; relu fused) -------------------
__global__ __launch_bounds__(192)
void pool_kernel(const __half* __restrict__ f2, const int* __restrict__ bidx,
                 int N, float* __restrict__ pooled)
{
    __shared__ int sb[128];
    const int n0 = blockIdx.x * 128;
    const int t  = threadIdx.x;
    if (n0 >= N) return;
    const int nEnd = min(n0 + 128, N);
    if (t < 128 && (n0 + t) < N) sb[t] = bidx[n0 + t];
    __syncthreads();

    int cur = sb[0];
    float acc = 0.f;
    for (int n = n0; n < nEnd; ++n) {
        int b = sb[n - n0];
        if (b != cur) {
            atomicAdd(&pooled[cur * DH + t], acc);
            acc = 0.f;
            cur = b;
        }
        acc += fmaxf(__half2float(f2[(long)n * DH + t]), 0.f);
    }
    atomicAdd(&pooled[cur * DH + t], acc);
}

// ---------------- final MLP ------------------------------------------------------
__global__ __launch_bounds__(256)
void mlp_kernel(const float* __restrict__ pooled,
                const float* __restrict__ A1, const float* __restrict__ ba1,
                const float* __restrict__ A2, const float* __restrict__ ba2,
                float* __restrict__ out)
{
    const int g = blockIdx.x;
    __shared__ float sp[DH];
    __shared__ float sh[256];
    const int t = threadIdx.x;
    if (t < DH) sp[t] = pooled[g * DH + t];
    __syncthreads();

    float acc = ba1[t];
#pragma unroll 8
    for (int k = 0; k < DH; ++k)
        acc += sp[k] * A1[k * 256 + t];
    sh[t] = fmaxf(acc, 0.f);
    __syncthreads();

    if (t < 10) {
        float o = ba2[t];
#pragma unroll 8
        for (int j = 0; j < 256; ++j)
            o += sh[j] * A2[j * 10 + t];
        out[g * 10 + t] = o;
    }
}

// ---------------- launcher -------------------------------------------------------
extern "C" void kernel_launch(void* const* d_in, const int* in_sizes, int n_in,
                              void* d_out, int out_size)
{
    const float* x     = (const float*)d_in[0];
    const int*   map00 = (const int*)d_in[1];
    const int*   map01 = (const int*)d_in[2];
    const int*   map02 = (const int*)d_in[3];
    const int*   map10 = (const int*)d_in[4];
    const int*   map11 = (const int*)d_in[5];
    const int*   map12 = (const int*)d_in[6];
    const int*   bidx  = (const int*)d_in[7];
    const float* W00 = (const float*)d_in[9];
    const float* b00 = (const float*)d_in[10];
    const float* W01 = (const float*)d_in[11];
    const float* b01 = (const float*)d_in[12];
    const float* W02 = (const float*)d_in[13];
    const float* b02 = (const float*)d_in[14];
    const float* W10 = (const float*)d_in[15];
    const float* b10 = (const float*)d_in[16];
    const float* W11 = (const float*)d_in[17];
    const float* b11 = (const float*)d_in[18];
    const float* W12 = (const float*)d_in[19];
    const float* b12 = (const float*)d_in[20];
    const float* A1  = (const float*)d_in[21];
    const float* ba1 = (const float*)d_in[22];
    const float* A2  = (const float*)d_in[23];
    const float* ba2 = (const float*)d_in[24];

    const int DIN = 128;
    const int N = in_sizes[0] / DIN;
    const int E = in_sizes[1] / 2;
    const int B = out_size / 10;

    __half *p_h0, *p_f1, *p_h1, *p_f2;
    float  *p_pool;
    cudaGetSymbolAddress((void**)&p_h0, g_h0);
    cudaGetSymbolAddress((void**)&p_f1, g_f1);
    cudaGetSymbolAddress((void**)&p_h1, g_h1);
    cudaGetSymbolAddress((void**)&p_f2, g_f2);
    cudaGetSymbolAddress((void**)&p_pool, g_pool);

    // 1) zero f1, f2 (half), pooled (fp32)
    {
        int n16_feat = N * DH / 8;
        int n4_pool  = B * DH / 4;
        int blocks = (n16_feat + 255) / 256;
        zero_all_kernel<<<blocks, 256>>>(n16_feat, n4_pool);
    }

    const int mBlocks = (N + 127) / 128;

    // 2) layer0 linear (tensor cores): h0 = x @ [W00|W01|W02] + b
    gemm_tc_kernel<float, false><<<dim3(mBlocks, 3), 256>>>(
        x, N, DIN, W00, W01, W02, b00, b01, b02, p_h0);

    // 3) layer0 scatter
    {
        int blocks = (E + 31) / 32;
        scatter_kernel<<<dim3(blocks, 3), 256>>>(p_h0, map00, map01, map02, E, p_f1);
    }

    // 4) layer1 linear (tensor cores, relu on load)
    gemm_tc_kernel<__half, true><<<dim3(mBlocks, 3), 256>>>(
        p_f1, N, DH, W10, W11, W12, b10, b11, b12, p_h1);

    // 5) layer1 scatter
    {
        int blocks = (E + 31) / 32;
        scatter_kernel<<<dim3(blocks, 3), 256>>>(p_h1, map10, map11, map12, E, p_f2);
    }

    // 6) pooling (relu fused)
    pool_kernel<<<(N + 127) / 128, 192>>>(p_f2, bidx, N, p_pool);

    // 7) MLP head
    mlp_kernel<<<B, 256>>>(p_pool, A1, ba1, A2, ba2, (float*)d_out);
}

// round 13
// speedup vs baseline: 1.9112x; 1.0256x over previous
#include <cuda_runtime.h>
#include <cuda_fp16.h>
#include <cstdint>

#define NMAX   50048
#define DH     192
#define BMAXP  256

// ---------------- scratch (static device globals) ----------------
__device__ __half g_h0[NMAX * DH];
__device__ __half g_f1[NMAX * DH];
__device__ __half g_h1[NMAX * DH];
__device__ __half g_f2[NMAX * DH];
__device__ float  g_pool[BMAXP * DH];

// ---------------- HMMA helpers ----------------
__device__ __forceinline__ uint32_t smem_u32(const void* p) {
    return (uint32_t)__cvta_generic_to_shared(p);
}
__device__ __forceinline__ void ldm_x4(uint32_t& r0, uint32_t& r1, uint32_t& r2,
                                       uint32_t& r3, uint32_t addr) {
    asm volatile("ldmatrix.sync.aligned.m8n8.x4.shared.b16 {%0,%1,%2,%3}, [%4];"
                 : "=r"(r0), "=r"(r1), "=r"(r2), "=r"(r3) : "r"(addr));
}
__device__ __forceinline__ void ldm_x4_t(uint32_t& r0, uint32_t& r1, uint32_t& r2,
                                         uint32_t& r3, uint32_t addr) {
    asm volatile("ldmatrix.sync.aligned.m8n8.x4.trans.shared.b16 {%0,%1,%2,%3}, [%4];"
                 : "=r"(r0), "=r"(r1), "=r"(r2), "=r"(r3) : "r"(addr));
}
__device__ __forceinline__ void mma16816(float* d, const uint32_t* a, const uint32_t* b) {
    asm volatile(
        "mma.sync.aligned.m16n8k16.row.col.f32.f16.f16.f32 "
        "{%0,%1,%2,%3}, {%4,%5,%6,%7}, {%8,%9}, {%0,%1,%2,%3};"
        : "+f"(d[0]), "+f"(d[1]), "+f"(d[2]), "+f"(d[3])
        : "r"(a[0]), "r"(a[1]), "r"(a[2]), "r"(a[3]), "r"(b[0]), "r"(b[1]));
}

// ---------------- tensor-core GEMM, double-buffered A, full-W smem -----------
// C[:, mker*64 : +64] = act(X) @ W_mker + b_mker    (fp32 accum, fp16 out)
// Also zeroes Z[:, mker*64:+64] for the following scatter pass, and (optionally,
// from block (0,0)) zeroes the pooled buffer.
// BM=128, BN=64, BK=32, 256 threads = 8 warps (4m x 2n), each warp 32x32.
#define A_STR 40   // halves per A smem row (pad 32 -> 40); 80B stride, conflict-free
#define B_STR 72   // halves per B smem row (pad 64 -> 72); 144B stride, conflict-free
#define KMAX  192

template <typename TIN, bool RELU, bool ZPOOL>
__global__ __launch_bounds__(256, 2)
void gemm_tc_kernel(const TIN* __restrict__ X, int N, int K,
                    const float* __restrict__ W0, const float* __restrict__ W1,
                    const float* __restrict__ W2,
                    const float* __restrict__ b0, const float* __restrict__ b1,
                    const float* __restrict__ b2,
                    __half* __restrict__ C,
                    __half* __restrict__ Z,
                    float* __restrict__ zpool, int zpool_n4)
{
    const int m0   = blockIdx.x * 128;
    const int mker = blockIdx.y;
    const float* __restrict__ W    = (mker == 0) ? W0 : (mker == 1 ? W1 : W2);
    const float* __restrict__ bias = (mker == 0) ? b0 : (mker == 1 ? b1 : b2);

    __shared__ __half As[2][128][A_STR];   // 20480 B
    __shared__ __half Bs[KMAX][B_STR];     // 27648 B  (total 48128 <= 48K)

    const int t    = threadIdx.x;
    const int lane = t & 31;
    const int wid  = t >> 5;
    const int wm   = wid >> 1;
    const int wn   = wid & 1;

    // ---- fused zeroing of the scatter destination slice ----
    {
        uint4 z = make_uint4(0u, 0u, 0u, 0u);
#pragma unroll
        for (int i = t; i < 128 * 8; i += 256) {
            int row = i >> 3, c8 = i & 7;
            int gr = m0 + row;
            if (gr < N)
                *reinterpret_cast<uint4*>(&Z[(long)gr * DH + mker * 64 + c8 * 8]) = z;
        }
    }
    // ---- fused zeroing of pooled buffer (one block only) ----
    if (ZPOOL && blockIdx.x == 0 && mker == 0) {
        for (int i = t; i < zpool_n4; i += 256)
            reinterpret_cast<float4*>(zpool)[i] = make_float4(0.f, 0.f, 0.f, 0.f);
    }

    // ---- load ALL of W into smem (fp32 -> fp16), K x 64 ----
    for (int idx = t; idx < K * 16; idx += 256) {
        int k  = idx >> 4;
        int n4 = idx & 15;
        float4 w = *reinterpret_cast<const float4*>(&W[(long)k * 64 + n4 * 4]);
        *reinterpret_cast<__half2*>(&Bs[k][n4 * 4])     = __floats2half2_rn(w.x, w.y);
        *reinterpret_cast<__half2*>(&Bs[k][n4 * 4 + 2]) = __floats2half2_rn(w.z, w.w);
    }

    const int iters = K >> 5;

    // A prefetch registers
    float4 va[4];
    uint4  ua[2];

    auto ldA = [&](int kk) {
        if constexpr (sizeof(TIN) == 4) {
#pragma unroll
            for (int it = 0; it < 4; ++it) {
                int idx = t + it * 256;
                int row = idx >> 3, c4 = idx & 7, gr = m0 + row;
                va[it] = make_float4(0.f, 0.f, 0.f, 0.f);
                if (gr < N)
                    va[it] = *reinterpret_cast<const float4*>(
                        &((const float*)X)[(long)gr * K + kk + c4 * 4]);
            }
        } else {
#pragma unroll
            for (int it = 0; it < 2; ++it) {
                int idx = t + it * 256;
                int row = idx >> 2, hp = idx & 3, gr = m0 + row;
                ua[it] = make_uint4(0u, 0u, 0u, 0u);
                if (gr < N)
                    ua[it] = *reinterpret_cast<const uint4*>(
                        &((const __half*)X)[(long)gr * K + kk + hp * 8]);
            }
        }
    };
    auto stA = [&](int buf) {
        if constexpr (sizeof(TIN) == 4) {
#pragma unroll
            for (int it = 0; it < 4; ++it) {
                int idx = t + it * 256;
                int row = idx >> 3, c4 = idx & 7;
                *reinterpret_cast<__half2*>(&As[buf][row][c4 * 4]) =
                    __floats2half2_rn(va[it].x, va[it].y);
                *reinterpret_cast<__half2*>(&As[buf][row][c4 * 4 + 2]) =
                    __floats2half2_rn(va[it].z, va[it].w);
            }
        } else {
#pragma unroll
            for (int it = 0; it < 2; ++it) {
                int idx = t + it * 256;
                int row = idx >> 2, hp = idx & 3;
                uint4 u = ua[it];
                if (RELU) {
                    __half2* hh = reinterpret_cast<__half2*>(&u);
                    __half2 z = __float2half2_rn(0.f);
#pragma unroll
                    for (int j = 0; j < 4; ++j) hh[j] = __hmax2(hh[j], z);
                }
                *reinterpret_cast<uint4*>(&As[buf][row][hp * 8]) = u;
            }
        }
    };

    float acc[2][4][4];
#pragma unroll
    for (int i = 0; i < 2; ++i)
#pragma unroll
        for (int j = 0; j < 4; ++j)
#pragma unroll
            for (int q = 0; q < 4; ++q) acc[i][j][q] = 0.f;

    ldA(0);
    stA(0);
    __syncthreads();   // Bs + As[0] ready

    for (int kt = 0; kt < iters; ++kt) {
        const int buf = kt & 1;
        if (kt + 1 < iters) ldA((kt + 1) * 32);   // prefetch next A tile (global)

#pragma unroll
        for (int k16i = 0; k16i < 2; ++k16i) {
            const int kb = kt * 32 + k16i * 16;   // row in Bs
            uint32_t af[2][4];
#pragma unroll
            for (int mi = 0; mi < 2; ++mi) {
                uint32_t addr = smem_u32(&As[buf][wm * 32 + mi * 16 + (lane & 15)]
                                            [k16i * 16 + (lane >> 4) * 8]);
                ldm_x4(af[mi][0], af[mi][1], af[mi][2], af[mi][3], addr);
            }
            uint32_t bf[4][2];
#pragma unroll
            for (int ni2 = 0; ni2 < 2; ++ni2) {
                int n0 = wn * 32 + ni2 * 16;
                uint32_t addr = smem_u32(&Bs[kb + (lane & 15)][n0 + (lane >> 4) * 8]);
                uint32_t r0, r1, r2, r3;
                ldm_x4_t(r0, r1, r2, r3, addr);
                bf[ni2 * 2][0]     = r0; bf[ni2 * 2][1]     = r1;
                bf[ni2 * 2 + 1][0] = r2; bf[ni2 * 2 + 1][1] = r3;
            }
#pragma unroll
            for (int mi = 0; mi < 2; ++mi)
#pragma unroll
                for (int ni = 0; ni < 4; ++ni)
                    mma16816(acc[mi][ni], af[mi], bf[ni]);
        }

        if (kt + 1 < iters) {
            stA(buf ^ 1);      // write next tile into the other buffer
            __syncthreads();   // ready for next iter; also protects As[buf] reads
        }
    }

    // ---- epilogue: + bias, fp16 store ----
#pragma unroll
    for (int mi = 0; mi < 2; ++mi) {
#pragma unroll
        for (int ni = 0; ni < 4; ++ni) {
            int col = wn * 32 + ni * 8 + (lane & 3) * 2;
            float bx = bias[col], by = bias[col + 1];
            int r0 = m0 + wm * 32 + mi * 16 + (lane >> 2);
            if (r0 < N) {
                __half2 h = __floats2half2_rn(acc[mi][ni][0] + bx, acc[mi][ni][1] + by);
                *reinterpret_cast<__half2*>(&C[(long)r0 * DH + mker * 64 + col]) = h;
            }
            int r1 = r0 + 8;
            if (r1 < N) {
                __half2 h = __floats2half2_rn(acc[mi][ni][2] + bx, acc[mi][ni][3] + by);
                *reinterpret_cast<__half2*>(&C[(long)r1 * DH + mker * 64 + col]) = h;
            }
        }
    }
}

// ---------------- gather + scatter_add over edges (fp16, v4.f16x2 red) -----------
__global__ __launch_bounds__(256)
void scatter_kernel(const __half* __restrict__ h,
                    const int* __restrict__ mA,
                    const int* __restrict__ mB,
                    const int* __restrict__ mC,
                    int E, __half* __restrict__ out)
{
    const int* __restrict__ mp =
        (blockIdx.y == 0) ? mA : (blockIdx.y == 1 ? mB : mC);
    const int moff = blockIdx.y * 64;

    __shared__ int sd[32], ss[32];
    const int e0 = blockIdx.x * 32;
    const int t  = threadIdx.x;
    if (t < 32) {
        int e = e0 + t;
        sd[t] = (e < E) ? mp[e] : -1;
    } else if (t < 64) {
        int e = e0 + t - 32;
        ss[t - 32] = (e < E) ? mp[E + e] : 0;
    }
    __syncthreads();

    const int le = t >> 3;
    const int q  = t & 7;
    const int dst = sd[le];
    if (dst < 0) return;
    const int src = ss[le];

    uint4 v = *reinterpret_cast<const uint4*>(&h[(long)src * DH + moff + q * 8]);
    const __half* o = &out[(long)dst * DH + moff + q * 8];
    asm volatile("red.global.add.noftz.v4.f16x2 [%0], {%1, %2, %3, %4};"
                 :: "l"(o), "r"(v.x), "r"(v.y), "r"(v.z), "r"(v.w)
                 : "memory");
}

// ---------------- batch pooling (batch_idx sorted; relu fused) -------------------
__global__ __launch_bounds__(192)
void pool_kernel(const __half* __restrict__ f2, const int* __restrict__ bidx,
                 int N, float* __restrict__ pooled)
{
    __shared__ int sb[128];
    const int n0 = blockIdx.x * 128;
    const int t  = threadIdx.x;
    if (n0 >= N) return;
    const int nEnd = min(n0 + 128, N);
    if (t < 128 && (n0 + t) < N) sb[t] = bidx[n0 + t];
    __syncthreads();

    int cur = sb[0];
    float acc = 0.f;
    for (int n = n0; n < nEnd; ++n) {
        int b = sb[n - n0];
        if (b != cur) {
            atomicAdd(&pooled[cur * DH + t], acc);
            acc = 0.f;
            cur = b;
        }
        acc += fmaxf(__half2float(f2[(long)n * DH + t]), 0.f);
    }
    atomicAdd(&pooled[cur * DH + t], acc);
}

// ---------------- final MLP ------------------------------------------------------
__global__ __launch_bounds__(256)
void mlp_kernel(const float* __restrict__ pooled,
                const float* __restrict__ A1, const float* __restrict__ ba1,
                const float* __restrict__ A2, const float* __restrict__ ba2,
                float* __restrict__ out)
{
    const int g = blockIdx.x;
    __shared__ float sp[DH];
    __shared__ float sh[256];
    const int t = threadIdx.x;
    if (t < DH) sp[t] = pooled[g * DH + t];
    __syncthreads();

    float acc = ba1[t];
#pragma unroll 8
    for (int k = 0; k < DH; ++k)
        acc += sp[k] * A1[k * 256 + t];
    sh[t] = fmaxf(acc, 0.f);
    __syncthreads();

    if (t < 10) {
        float o = ba2[t];
#pragma unroll 8
        for (int j = 0; j < 256; ++j)
            o += sh[j] * A2[j * 10 + t];
        out[g * 10 + t] = o;
    }
}

// ---------------- launcher -------------------------------------------------------
extern "C" void kernel_launch(void* const* d_in, const int* in_sizes, int n_in,
                              void* d_out, int out_size)
{
    const float* x     = (const float*)d_in[0];
    const int*   map00 = (const int*)d_in[1];
    const int*   map01 = (const int*)d_in[2];
    const int*   map02 = (const int*)d_in[3];
    const int*   map10 = (const int*)d_in[4];
    const int*   map11 = (const int*)d_in[5];
    const int*   map12 = (const int*)d_in[6];
    const int*   bidx  = (const int*)d_in[7];
    const float* W00 = (const float*)d_in[9];
    const float* b00 = (const float*)d_in[10];
    const float* W01 = (const float*)d_in[11];
    const float* b01 = (const float*)d_in[12];
    const float* W02 = (const float*)d_in[13];
    const float* b02 = (const float*)d_in[14];
    const float* W10 = (const float*)d_in[15];
    const float* b10 = (const float*)d_in[16];
    const float* W11 = (const float*)d_in[17];
    const float* b11 = (const float*)d_in[18];
    const float* W12 = (const float*)d_in[19];
    const float* b12 = (const float*)d_in[20];
    const float* A1  = (const float*)d_in[21];
    const float* ba1 = (const float*)d_in[22];
    const float* A2  = (const float*)d_in[23];
    const float* ba2 = (const float*)d_in[24];

    const int DIN = 128;
    const int N = in_sizes[0] / DIN;
    const int E = in_sizes[1] / 2;
    const int B = out_size / 10;

    __half *p_h0, *p_f1, *p_h1, *p_f2;
    float  *p_pool;
    cudaGetSymbolAddress((void**)&p_h0, g_h0);
    cudaGetSymbolAddress((void**)&p_f1, g_f1);
    cudaGetSymbolAddress((void**)&p_h1, g_h1);
    cudaGetSymbolAddress((void**)&p_f2, g_f2);
    cudaGetSymbolAddress((void**)&p_pool, g_pool);

    const int mBlocks = (N + 127) / 128;

    // 1) layer0 linear (tensor cores, double-buffered) — also zeroes f1 slices
    gemm_tc_kernel<float, false, false><<<dim3(mBlocks, 3), 256>>>(
        x, N, DIN, W00, W01, W02, b00, b01, b02, p_h0, p_f1, nullptr, 0);

    // 2) layer0 scatter: f1[dst] += h0[src]
    {
        int blocks = (E + 31) / 32;
        scatter_kernel<<<dim3(blocks, 3), 256>>>(p_h0, map00, map01, map02, E, p_f1);
    }

    // 3) layer1 linear (relu on load) — also zeroes f2 slices and pooled
    gemm_tc_kernel<__half, true, true><<<dim3(mBlocks, 3), 256>>>(
        p_f1, N, DH, W10, W11, W12, b10, b11, b12, p_h1, p_f2, p_pool, B * DH / 4);

    // 4) layer1 scatter: f2[dst] += h1[src]
    {
        int blocks = (E + 31) / 32;
        scatter_kernel<<<dim3(blocks, 3), 256>>>(p_h1, map10, map11, map12, E, p_f2);
    }

    // 5) pooling (relu fused)
    pool_kernel<<<(N + 127) / 128, 192>>>(p_f2, bidx, N, p_pool);

    // 6) MLP head
    mlp_kernel<<<B, 256>>>(p_pool, A1, ba1, A2, ba2, (float*)d_out);
}